// round 8
// baseline (speedup 1.0000x reference)
#include <cuda_runtime.h>
#include <cuda_fp16.h>
#include <cstdint>

// ---------------------------------------------------------------------------
// Problem constants
// ---------------------------------------------------------------------------
#define BATCH   8
#define TSTEPS  512
#define NEMBD   512
#define NHID    1024
#define VOCAB   32000
#define NROWS   (BATCH * TSTEPS)        // 4096
#define NG3     (3 * NHID)              // 3072

// GRU persistent kernel config (R4 shape: 128 blocks x 8 cols, 16 warps)
#define GRU_BLOCKS   128
#define GRU_THREADS  512
#define WK          1032                // row stride (halves)

// GRU SMEM layout
#define WSM_BYTES   (24 * WK * 2)       // 49536  fp16 weights [gate*8+col][k]
#define HSM_BYTES   (8  * WK * 2)       // 16512  fp16 staged h / r*h
#define PBUF_FLOATS (16 * 2 * 64)       // 2048   fp32 partials [warp][gate][64]
#define XBUF_FLOATS 192
#define ZSM_FLOATS  64
#define HPSM_FLOATS 64
#define BSM_FLOATS  24
#define GRU_SMEM_BYTES (WSM_BYTES + HSM_BYTES + \
    (PBUF_FLOATS + XBUF_FLOATS + ZSM_FLOATS + HPSM_FLOATS + BSM_FLOATS) * 4)

// ---------------------------------------------------------------------------
// Device scratch (host resolves ONLY via cudaGetSymbolAddress)
// ---------------------------------------------------------------------------
__device__ __half              g_h16[BATCH * NHID];          // carry h (fp16)
__device__ __half              g_rh16[BATCH * NHID];         // r*h broadcast (fp16)
__device__ __half              g_hs[(size_t)NROWS * NHID];   // hidden states (fp16)
__device__ __half              g_wlm[(size_t)NHID * VOCAB];  // lm head weights fp16
__device__ __half              g_emb[(size_t)NROWS * NEMBD]; // gathered embeddings fp16
__device__ __half              g_wx[(size_t)NEMBD * NG3];    // x-part weights fp16
__device__ float               g_xp[(size_t)NROWS * NG3];    // precomputed x-projections
__device__ unsigned long long  g_arrive[GRU_BLOCKS];         // per-block arrival slots
__device__ unsigned long long  g_go_pad0[16];                // line separation
__device__ unsigned long long  g_go;                         // broadcast release flag
__device__ unsigned long long  g_go_pad1[15];
__device__ float               g_logits_fb[(size_t)NROWS * VOCAB];

// ---------------------------------------------------------------------------
// Barrier primitives: slot arrival + monitor sweep + broadcast go-flag.
// No atomics, no nanosleep. Tokens strictly increase across graph replays.
// ---------------------------------------------------------------------------
__device__ __forceinline__ unsigned long long ld_acq(const unsigned long long* p) {
    unsigned long long v;
    asm volatile("ld.acquire.gpu.global.u64 %0, [%1];" : "=l"(v) : "l"(p) : "memory");
    return v;
}
__device__ __forceinline__ void st_rel(unsigned long long* p, unsigned long long v) {
    asm volatile("st.release.gpu.global.u64 [%0], %1;" :: "l"(p), "l"(v) : "memory");
}

// Called by all 512 threads of every block. blockIdx.x==0 is the monitor.
__device__ __forceinline__ void group_barrier(unsigned long long tok) {
    __syncthreads();
    if (blockIdx.x == 0) {
        const int warp = threadIdx.x >> 5;
        const int lane = threadIdx.x & 31;
        if (warp == 0) {
            if (lane == 0) st_rel(&g_arrive[0], tok);
            // sweep all 128 slots: 4 per lane
            for (;;) {
                unsigned long long v0 = ld_acq(&g_arrive[lane]);
                unsigned long long v1 = ld_acq(&g_arrive[lane + 32]);
                unsigned long long v2 = ld_acq(&g_arrive[lane + 64]);
                unsigned long long v3 = ld_acq(&g_arrive[lane + 96]);
                bool ok = (v0 >= tok) && (v1 >= tok) && (v2 >= tok) && (v3 >= tok);
                if (__all_sync(0xffffffffu, ok)) break;
            }
            if (lane == 0) st_rel(&g_go, tok);
        }
        __syncthreads();
    } else {
        if (threadIdx.x == 0) {
            st_rel(&g_arrive[blockIdx.x], tok);
            while (ld_acq(&g_go) < tok) { }
        }
        __syncthreads();
    }
}

// ---------------------------------------------------------------------------
// mma m16n8k16 f16 -> f32
// ---------------------------------------------------------------------------
__device__ __forceinline__ void mma16816(float& c0, float& c1, float& c2, float& c3,
                                         unsigned a0, unsigned a1, unsigned a2, unsigned a3,
                                         unsigned b0, unsigned b1) {
    asm volatile(
        "mma.sync.aligned.m16n8k16.row.col.f32.f16.f16.f32 "
        "{%0,%1,%2,%3}, {%4,%5,%6,%7}, {%8,%9}, {%0,%1,%2,%3};\n"
        : "+f"(c0), "+f"(c1), "+f"(c2), "+f"(c3)
        : "r"(a0), "r"(a1), "r"(a2), "r"(a3), "r"(b0), "r"(b1));
}

// ---------------------------------------------------------------------------
// Persistent GRU scan (R4 structure, new barrier). Block owns cols
// [colbase, colbase+8). Warp w: K slice [w*64, w*64+64).
// ---------------------------------------------------------------------------
__global__ void __launch_bounds__(GRU_THREADS, 1)
gru_kernel(const float* __restrict__ start,
           const float* __restrict__ Wz, const float* __restrict__ bz,
           const float* __restrict__ Wr, const float* __restrict__ br,
           const float* __restrict__ Wh, const float* __restrict__ bh) {
    extern __shared__ char smem[];
    __half* wsm  = (__half*)smem;                          // [24][WK]
    __half* hsm  = (__half*)(smem + WSM_BYTES);            // [8][WK]
    float*  pbuf = (float*)(smem + WSM_BYTES + HSM_BYTES); // [16][2][64]
    float*  xbuf = pbuf + PBUF_FLOATS;                     // [192]
    float*  zsm  = xbuf + XBUF_FLOATS;                     // [64]
    float*  hpsm = zsm + ZSM_FLOATS;                       // [64] fp32 carried h
    float*  bsm  = hpsm + HPSM_FLOATS;                     // [24]

    const int tid     = threadIdx.x;
    const int warp    = tid >> 5;
    const int lane    = tid & 31;
    const int colbase = blockIdx.x * 8;

    // token base: g_go is stable from the previous launch; every block reads
    // it BEFORE its first arrival, so the base is race-free and replay-safe.
    const unsigned long long tok_base = ld_acq(&g_go);
    unsigned long long bctr = 0;

    // --- init: weights fp16 [gate*8+col][k], biases, carried h ---
    for (int i = tid; i < 24 * 1024; i += GRU_THREADS) {
        int j = i >> 10, k = i & 1023;             // j = gate*8+col
        int g = j >> 3;
        const float* W = (g == 0) ? Wz : ((g == 1) ? Wr : Wh);
        wsm[j * WK + k] = __float2half(W[(size_t)(NEMBD + k) * NHID + colbase + (j & 7)]);
    }
    if (tid < 24) bsm[tid] = (tid < 8 ? bz[colbase + tid]
                              : tid < 16 ? br[colbase + tid - 8]
                                         : bh[colbase + tid - 16]);
    if (tid < 64) hpsm[tid] = start[colbase + (tid & 7)];

    const float4* start4 = (const float4*)start;
    const uint4*  h16v   = (const uint4*)g_h16;
    const uint4*  rh16v  = (const uint4*)g_rh16;

    const int xb   = tid / 24;                  // tid<192: batch
    const int xrem = tid - xb * 24;             // gate*8+j

    const int frow = lane >> 2;                 // batch row (m) / col (n)
    const int fk   = (lane & 3) * 2;            // k pair
    const int kbase = warp * 64;

    for (int t = 0; t < TSTEPS; ++t) {
        // prefetch Xproj for this step
        float xpre = 0.f;
        if (tid < 192)
            xpre = g_xp[((size_t)(xb * TSTEPS + t)) * NG3 + (xrem >> 3) * NHID + colbase + (xrem & 7)];

        // ---- stage h rows 0-7 (fp16) into SMEM ----
        if (t == 0) {
            for (int i = tid; i < 1024; i += GRU_THREADS) {
                int b = i >> 7, seg = i & 127;
                float4 v0 = start4[seg * 2], v1 = start4[seg * 2 + 1];
                __half2 h0 = __floats2half2_rn(v0.x, v0.y);
                __half2 h1 = __floats2half2_rn(v0.z, v0.w);
                __half2 h2 = __floats2half2_rn(v1.x, v1.y);
                __half2 h3 = __floats2half2_rn(v1.z, v1.w);
                uint4 u;
                u.x = *(unsigned*)&h0; u.y = *(unsigned*)&h1;
                u.z = *(unsigned*)&h2; u.w = *(unsigned*)&h3;
                *(uint4*)&hsm[b * WK + seg * 8] = u;
            }
        } else {
            for (int i = tid; i < 1024; i += GRU_THREADS) {
                int b = i >> 7, seg = i & 127;
                *(uint4*)&hsm[b * WK + seg * 8] = h16v[b * 128 + seg];
            }
        }
        __syncthreads();

        // ---- Phase A: z and r ----
        {
            float cz0 = 0, cz1 = 0, cz2 = 0, cz3 = 0;
            float cr0 = 0, cr1 = 0, cr2 = 0, cr3 = 0;
#pragma unroll
            for (int c = 0; c < 4; c++) {
                int k0 = kbase + c * 16;
                unsigned a0 = *(const unsigned*)&hsm[frow * WK + k0 + fk];
                unsigned a2 = *(const unsigned*)&hsm[frow * WK + k0 + 8 + fk];
                unsigned bz0 = *(const unsigned*)&wsm[frow * WK + k0 + fk];
                unsigned bz1 = *(const unsigned*)&wsm[frow * WK + k0 + 8 + fk];
                unsigned br0 = *(const unsigned*)&wsm[(8 + frow) * WK + k0 + fk];
                unsigned br1 = *(const unsigned*)&wsm[(8 + frow) * WK + k0 + 8 + fk];
                mma16816(cz0, cz1, cz2, cz3, a0, 0u, a2, 0u, bz0, bz1);
                mma16816(cr0, cr1, cr2, cr3, a0, 0u, a2, 0u, br0, br1);
            }
            pbuf[(warp * 2 + 0) * 64 + frow * 8 + fk]     = cz0;
            pbuf[(warp * 2 + 0) * 64 + frow * 8 + fk + 1] = cz1;
            pbuf[(warp * 2 + 1) * 64 + frow * 8 + fk]     = cr0;
            pbuf[(warp * 2 + 1) * 64 + frow * 8 + fk + 1] = cr1;
        }
        if (tid < 192) xbuf[tid] = xpre;
        __syncthreads();

        // reduce + activations
        if (tid < 128) {
            int b = tid >> 4, jj = tid & 15;
            int g = jj >> 3, j = jj & 7;
            float s = 0.f;
#pragma unroll
            for (int w = 0; w < 16; w++) s += pbuf[(w * 2 + g) * 64 + b * 8 + j];
            if (g == 0) {
                float z = 1.f / (1.f + __expf(-(s + xbuf[b * 24 + j] + bsm[j])));
                zsm[b * 8 + j] = z;
            } else {
                float r = 1.f / (1.f + __expf(-(s + xbuf[b * 24 + 8 + j] + bsm[8 + j])));
                g_rh16[b * NHID + colbase + j] = __float2half(r * hpsm[b * 8 + j]);
            }
        }
        group_barrier(tok_base + (++bctr));

        // ---- stage r*h ----
        for (int i = tid; i < 1024; i += GRU_THREADS) {
            int b = i >> 7, seg = i & 127;
            *(uint4*)&hsm[b * WK + seg * 8] = rh16v[b * 128 + seg];
        }
        __syncthreads();

        // ---- Phase B: hbar ----
        {
            float c0 = 0, c1 = 0, c2 = 0, c3 = 0;
#pragma unroll
            for (int c = 0; c < 4; c++) {
                int k0 = kbase + c * 16;
                unsigned a0 = *(const unsigned*)&hsm[frow * WK + k0 + fk];
                unsigned a2 = *(const unsigned*)&hsm[frow * WK + k0 + 8 + fk];
                unsigned bh0 = *(const unsigned*)&wsm[(16 + frow) * WK + k0 + fk];
                unsigned bh1 = *(const unsigned*)&wsm[(16 + frow) * WK + k0 + 8 + fk];
                mma16816(c0, c1, c2, c3, a0, 0u, a2, 0u, bh0, bh1);
            }
            pbuf[warp * 2 * 64 + frow * 8 + fk]     = c0;
            pbuf[warp * 2 * 64 + frow * 8 + fk + 1] = c1;
        }
        __syncthreads();

        if (tid < 64) {
            int b = tid >> 3, j = tid & 7;
            float s = 0.f;
#pragma unroll
            for (int w = 0; w < 16; w++) s += pbuf[w * 2 * 64 + b * 8 + j];
            float hbar  = tanhf(s + xbuf[b * 24 + 16 + j] + bsm[16 + j]);
            float hprev = hpsm[tid];
            float z     = zsm[tid];
            float hn    = hprev + z * (hbar - hprev);
            hpsm[tid] = hn;
            __half hh = __float2half(hn);
            int c = colbase + j;
            g_h16[b * NHID + c] = hh;
            g_hs[(size_t)(b * TSTEPS + t) * NHID + c] = hh;
        }
        group_barrier(tok_base + (++bctr));
    }
}

// ---------------------------------------------------------------------------
// Prep kernels
// ---------------------------------------------------------------------------
__global__ void cvt_half2(const float2* __restrict__ src, __half2* __restrict__ dst, int n2) {
    int i = blockIdx.x * blockDim.x + threadIdx.x;
    int stride = gridDim.x * blockDim.x;
    for (; i < n2; i += stride) {
        float2 v = src[i];
        dst[i] = __floats2half2_rn(v.x, v.y);
    }
}

__global__ void build_wx(const float* __restrict__ Wz, const float* __restrict__ Wr,
                         const float* __restrict__ Wh, __half* __restrict__ dst) {
    int i = blockIdx.x * blockDim.x + threadIdx.x;
    if (i >= NEMBD * NG3) return;
    int k = i / NG3, c = i - k * NG3;
    int g = c >> 10, j = c & 1023;
    const float* W = (g == 0) ? Wz : ((g == 1) ? Wr : Wh);
    dst[i] = __float2half(W[(size_t)k * NHID + j]);
}

__global__ void gather_emb(const int* __restrict__ idx, const float* __restrict__ wte,
                           __half* __restrict__ dst) {
    int r = blockIdx.x;
    int tok = idx[r];
    float4 v = ((const float4*)(wte + (size_t)tok * NEMBD))[threadIdx.x];
    __half2* d = (__half2*)(dst + (size_t)r * NEMBD);
    d[threadIdx.x * 2]     = __floats2half2_rn(v.x, v.y);
    d[threadIdx.x * 2 + 1] = __floats2half2_rn(v.z, v.w);
}

// ---------------------------------------------------------------------------
// fp16 tensor-core GEMM: C[M,NCOLS] = A[M,KDIM] * B[KDIM,NCOLS] (+bias)
// ---------------------------------------------------------------------------
#define AS_STRIDE 40
#define BS_STRIDE 42

template<int KDIM, int NCOLS2, bool HAS_BIAS>
__global__ void __launch_bounds__(256)
gemm_kernel(const __half* __restrict__ A, const __half* __restrict__ Bw,
            const float* __restrict__ bias, float* __restrict__ C) {
    const int bx = blockIdx.x, by = blockIdx.y;
    const int tid = threadIdx.x, warp = tid >> 5, lane = tid & 31;
    const int wm = warp >> 2, wn = warp & 3;
    __shared__ __half As[128 * AS_STRIDE];
    __shared__ __half Bs[128 * BS_STRIDE];

    float acc[4][4][4];
#pragma unroll
    for (int a = 0; a < 4; a++)
#pragma unroll
        for (int b = 0; b < 4; b++)
#pragma unroll
            for (int c = 0; c < 4; c++) acc[a][b][c] = 0.f;

    const int m0 = by * 128, n0 = bx * 128;

    for (int k0 = 0; k0 < KDIM; k0 += 32) {
#pragma unroll
        for (int i = tid; i < 512; i += 256) {
            int row = i >> 2, seg = i & 3;
            *(uint4*)&As[row * AS_STRIDE + seg * 8] =
                *(const uint4*)&A[(size_t)(m0 + row) * KDIM + k0 + seg * 8];
        }
#pragma unroll
        for (int i = tid; i < 2048; i += 256) {
            int k = i >> 6, np = i & 63;
            __half2 h2 = *(const __half2*)(Bw + (size_t)(k0 + k) * NCOLS2 + n0 + np * 2);
            Bs[(np * 2)     * BS_STRIDE + k] = __low2half(h2);
            Bs[(np * 2 + 1) * BS_STRIDE + k] = __high2half(h2);
        }
        __syncthreads();

#pragma unroll
        for (int kk = 0; kk < 2; kk++) {
            unsigned a[4][4], b[4][2];
            const int kc = kk * 16 + (lane & 3) * 2;
            const int r  = lane >> 2;
#pragma unroll
            for (int mt = 0; mt < 4; mt++) {
                int rr = wm * 64 + mt * 16 + r;
                a[mt][0] = *(const unsigned*)&As[rr * AS_STRIDE + kc];
                a[mt][1] = *(const unsigned*)&As[(rr + 8) * AS_STRIDE + kc];
                a[mt][2] = *(const unsigned*)&As[rr * AS_STRIDE + kc + 8];
                a[mt][3] = *(const unsigned*)&As[(rr + 8) * AS_STRIDE + kc + 8];
            }
#pragma unroll
            for (int nt = 0; nt < 4; nt++) {
                int nn = wn * 32 + nt * 8 + r;
                b[nt][0] = *(const unsigned*)&Bs[nn * BS_STRIDE + kc];
                b[nt][1] = *(const unsigned*)&Bs[nn * BS_STRIDE + kc + 8];
            }
#pragma unroll
            for (int mt = 0; mt < 4; mt++)
#pragma unroll
                for (int nt = 0; nt < 4; nt++)
                    mma16816(acc[mt][nt][0], acc[mt][nt][1], acc[mt][nt][2], acc[mt][nt][3],
                             a[mt][0], a[mt][1], a[mt][2], a[mt][3], b[nt][0], b[nt][1]);
        }
        __syncthreads();
    }

#pragma unroll
    for (int mt = 0; mt < 4; mt++) {
#pragma unroll
        for (int nt = 0; nt < 4; nt++) {
            int gr = m0 + wm * 64 + mt * 16 + (lane >> 2);
            int gc = n0 + wn * 32 + nt * 8 + (lane & 3) * 2;
            float b0 = 0.f, b1 = 0.f;
            if (HAS_BIAS) { b0 = bias[gc]; b1 = bias[gc + 1]; }
            float2 v0 = make_float2(acc[mt][nt][0] + b0, acc[mt][nt][1] + b1);
            float2 v1 = make_float2(acc[mt][nt][2] + b0, acc[mt][nt][3] + b1);
            *(float2*)&C[(size_t)gr * NCOLS2 + gc]       = v0;
            *(float2*)&C[(size_t)(gr + 8) * NCOLS2 + gc] = v1;
        }
    }
}

// ---------------------------------------------------------------------------
// Loss
// ---------------------------------------------------------------------------
__global__ void __launch_bounds__(256)
loss_kernel(const float* __restrict__ logits, const int* __restrict__ targets,
            float* __restrict__ out_loss) {
    const int row = blockIdx.x;
    const float* lr = logits + (size_t)row * VOCAB;
    const int tid = threadIdx.x;

    float m = -1e30f, s = 0.f;
    for (int i = tid; i < VOCAB; i += 256) {
        float v = lr[i];
        float nm = fmaxf(m, v);
        s = s * __expf(m - nm) + __expf(v - nm);
        m = nm;
    }
    __shared__ float sm_m[256], sm_s[256];
    sm_m[tid] = m; sm_s[tid] = s;
    __syncthreads();
    for (int off = 128; off > 0; off >>= 1) {
        if (tid < off) {
            float m2 = sm_m[tid + off], s2 = sm_s[tid + off];
            float m1 = sm_m[tid],       s1 = sm_s[tid];
            float nm = fmaxf(m1, m2);
            sm_s[tid] = s1 * __expf(m1 - nm) + s2 * __expf(m2 - nm);
            sm_m[tid] = nm;
        }
        __syncthreads();
    }
    if (tid == 0) {
        float lse = sm_m[0] + logf(sm_s[0]);
        float tl  = lr[targets[row]];
        atomicAdd(out_loss, (lse - tl) * (1.0f / (float)NROWS));
    }
}

// ---------------------------------------------------------------------------
// Host entry
// ---------------------------------------------------------------------------
extern "C" void kernel_launch(void* const* d_in, const int* in_sizes, int n_in,
                              void* d_out, int out_size) {
    const int*   idx   = (const int*)d_in[0];
    const int*   tgt   = (const int*)d_in[1];
    const float* wte   = (const float*)d_in[2];
    const float* start = (const float*)d_in[3];
    const float* Wz    = (const float*)d_in[4];
    const float* bz    = (const float*)d_in[5];
    const float* Wr    = (const float*)d_in[6];
    const float* br    = (const float*)d_in[7];
    const float* Wh    = (const float*)d_in[8];
    const float* bh    = (const float*)d_in[9];
    const float* lmW   = (const float*)d_in[10];
    const float* lmb   = (const float*)d_in[11];

    void *p_hs, *p_wlm, *p_fb, *p_emb, *p_wx, *p_xp;
    cudaGetSymbolAddress(&p_hs,  g_hs);
    cudaGetSymbolAddress(&p_wlm, g_wlm);
    cudaGetSymbolAddress(&p_fb,  g_logits_fb);
    cudaGetSymbolAddress(&p_emb, g_emb);
    cudaGetSymbolAddress(&p_wx,  g_wx);
    cudaGetSymbolAddress(&p_xp,  g_xp);
    __half* d_hs  = (__half*)p_hs;
    __half* d_wlm = (__half*)p_wlm;
    float*  d_fb  = (float*)p_fb;
    __half* d_emb = (__half*)p_emb;
    __half* d_wx  = (__half*)p_wx;
    float*  d_xp  = (float*)p_xp;

    cudaFuncSetAttribute(gru_kernel, cudaFuncAttributeMaxDynamicSharedMemorySize,
                         GRU_SMEM_BYTES);

    build_wx<<<(NEMBD * NG3 + 255) / 256, 256>>>(Wz, Wr, Wh, d_wx);
    gather_emb<<<NROWS, 128>>>(idx, wte, d_emb);

    gemm_kernel<NEMBD, NG3, false><<<dim3(NG3 / 128, NROWS / 128), 256>>>(
        d_emb, d_wx, nullptr, d_xp);

    gru_kernel<<<GRU_BLOCKS, GRU_THREADS, GRU_SMEM_BYTES>>>(start, Wz, bz, Wr, br, Wh, bh);

    cvt_half2<<<4096, 256>>>((const float2*)lmW, (__half2*)d_wlm, (NHID * VOCAB) / 2);
    const long long NL = (long long)NROWS * VOCAB;
    float* fo = (float*)d_out;
    float* logits = ((long long)out_size >= NL) ? fo : d_fb;
    gemm_kernel<NHID, VOCAB, true><<<dim3(VOCAB / 128, NROWS / 128), 256>>>(
        d_hs, d_wlm, lmb, logits);

    float* loss_ptr = nullptr;
    if ((long long)out_size >= NL + 1)      loss_ptr = fo + NL;
    else if ((long long)out_size < NL)      loss_ptr = fo;
    if (loss_ptr) {
        cudaMemsetAsync(loss_ptr, 0, sizeof(float));
        loss_kernel<<<NROWS, 256>>>(logits, tgt, loss_ptr);
    }
}

// round 9
// speedup vs baseline: 1.5678x; 1.5678x over previous
#include <cuda_runtime.h>
#include <cuda_fp16.h>
#include <cstdint>

// ---------------------------------------------------------------------------
// Problem constants
// ---------------------------------------------------------------------------
#define BATCH   8
#define TSTEPS  512
#define NEMBD   512
#define NHID    1024
#define VOCAB   32000
#define NROWS   (BATCH * TSTEPS)        // 4096
#define NG3     (3 * NHID)              // 3072

// GRU persistent kernel config (R4 exact: 128 blocks x 8 cols, 16 warps)
#define GRU_BLOCKS   128
#define GRU_THREADS  512
#define WK          1032                // row stride (halves)

// GRU SMEM layout (R4 exact)
#define WSM_BYTES   (24 * WK * 2)       // 49536  fp16 weights [gate*8+col][k]
#define HSM_BYTES   (8  * WK * 2)       // 16512  fp16 staged h / r*h
#define PBUF_FLOATS (16 * 2 * 64)       // 2048   fp32 partials [warp][gate][64]
#define XBUF_FLOATS 192
#define ZSM_FLOATS  64
#define HPSM_FLOATS 64
#define BSM_FLOATS  24
#define GRU_SMEM_BYTES (WSM_BYTES + HSM_BYTES + \
    (PBUF_FLOATS + XBUF_FLOATS + ZSM_FLOATS + HPSM_FLOATS + BSM_FLOATS) * 4)

// ---------------------------------------------------------------------------
// Device scratch (host resolves ONLY via cudaGetSymbolAddress)
// ---------------------------------------------------------------------------
__device__ __half              g_h16[BATCH * NHID];          // carry h (fp16)
__device__ __half              g_rh16[BATCH * NHID];         // r*h broadcast (fp16)
__device__ __half              g_hs[(size_t)NROWS * NHID];   // hidden states (fp16)
__device__ __half              g_wlm[(size_t)NHID * VOCAB];  // lm head weights fp16
__device__ __half              g_emb[(size_t)NROWS * NEMBD]; // gathered embeddings fp16
__device__ __half              g_wx[(size_t)NEMBD * NG3];    // x-part weights fp16
__device__ float               g_xp[(size_t)NROWS * NG3];    // precomputed x-projections
__device__ unsigned long long  g_ctrs[256];                  // barrier counters [0],[128]
__device__ float               g_logits_fb[(size_t)NROWS * VOCAB];

// ---------------------------------------------------------------------------
// Grid barrier (R4 exact): release-add + acquire-poll with nanosleep backoff.
// Cumulative ticket counter -> graph-replay-safe.
// ---------------------------------------------------------------------------
__device__ __forceinline__ void group_barrier(unsigned long long* ctr) {
    __syncthreads();
    if (threadIdx.x == 0) {
        unsigned long long one = 1ULL, old;
        asm volatile("atom.add.release.gpu.global.u64 %0, [%1], %2;"
                     : "=l"(old) : "l"(ctr), "l"(one) : "memory");
        unsigned long long target = ((old + 1ULL + (GRU_BLOCKS - 1)) / GRU_BLOCKS) * GRU_BLOCKS;
        unsigned long long cur;
        asm volatile("ld.acquire.gpu.global.u64 %0, [%1];" : "=l"(cur) : "l"(ctr) : "memory");
        while (cur < target) {
            __nanosleep(64);
            asm volatile("ld.acquire.gpu.global.u64 %0, [%1];" : "=l"(cur) : "l"(ctr) : "memory");
        }
    }
    __syncthreads();
}

// ---------------------------------------------------------------------------
// mma m16n8k16 f16 -> f32
// ---------------------------------------------------------------------------
__device__ __forceinline__ void mma16816(float& c0, float& c1, float& c2, float& c3,
                                         unsigned a0, unsigned a1, unsigned a2, unsigned a3,
                                         unsigned b0, unsigned b1) {
    asm volatile(
        "mma.sync.aligned.m16n8k16.row.col.f32.f16.f16.f32 "
        "{%0,%1,%2,%3}, {%4,%5,%6,%7}, {%8,%9}, {%0,%1,%2,%3};\n"
        : "+f"(c0), "+f"(c1), "+f"(c2), "+f"(c3)
        : "r"(a0), "r"(a1), "r"(a2), "r"(a3), "r"(b0), "r"(b1));
}

// ---------------------------------------------------------------------------
// Persistent GRU scan — R4 EXACT (best measured: 2.43 ms).
// ---------------------------------------------------------------------------
__global__ void __launch_bounds__(GRU_THREADS, 1)
gru_kernel(const float* __restrict__ start,
           const float* __restrict__ Wz, const float* __restrict__ bz,
           const float* __restrict__ Wr, const float* __restrict__ br,
           const float* __restrict__ Wh, const float* __restrict__ bh) {
    extern __shared__ char smem[];
    __half* wsm  = (__half*)smem;                          // [24][WK]
    __half* hsm  = (__half*)(smem + WSM_BYTES);            // [8][WK]
    float*  pbuf = (float*)(smem + WSM_BYTES + HSM_BYTES); // [16][2][64]
    float*  xbuf = pbuf + PBUF_FLOATS;                     // [192]
    float*  zsm  = xbuf + XBUF_FLOATS;                     // [64]
    float*  hpsm = zsm + ZSM_FLOATS;                       // [64] fp32 carried h
    float*  bsm  = hpsm + HPSM_FLOATS;                     // [24]

    const int tid     = threadIdx.x;
    const int warp    = tid >> 5;
    const int lane    = tid & 31;
    const int colbase = blockIdx.x * 8;

    for (int i = tid; i < 24 * 1024; i += GRU_THREADS) {
        int j = i >> 10, k = i & 1023;
        int g = j >> 3;
        const float* W = (g == 0) ? Wz : ((g == 1) ? Wr : Wh);
        wsm[j * WK + k] = __float2half(W[(size_t)(NEMBD + k) * NHID + colbase + (j & 7)]);
    }
    if (tid < 24) bsm[tid] = (tid < 8 ? bz[colbase + tid]
                              : tid < 16 ? br[colbase + tid - 8]
                                         : bh[colbase + tid - 16]);
    if (tid < 64) hpsm[tid] = start[colbase + (tid & 7)];

    const float4* start4 = (const float4*)start;
    const uint4*  h16v   = (const uint4*)g_h16;
    const uint4*  rh16v  = (const uint4*)g_rh16;

    const int xb   = tid / 24;
    const int xrem = tid - xb * 24;

    const int frow = lane >> 2;
    const int fk   = (lane & 3) * 2;
    const int kbase = warp * 64;

    for (int t = 0; t < TSTEPS; ++t) {
        float xpre = 0.f;
        if (tid < 192)
            xpre = g_xp[((size_t)(xb * TSTEPS + t)) * NG3 + (xrem >> 3) * NHID + colbase + (xrem & 7)];

        if (t == 0) {
            for (int i = tid; i < 1024; i += GRU_THREADS) {
                int b = i >> 7, seg = i & 127;
                float4 v0 = start4[seg * 2], v1 = start4[seg * 2 + 1];
                __half2 h0 = __floats2half2_rn(v0.x, v0.y);
                __half2 h1 = __floats2half2_rn(v0.z, v0.w);
                __half2 h2 = __floats2half2_rn(v1.x, v1.y);
                __half2 h3 = __floats2half2_rn(v1.z, v1.w);
                uint4 u;
                u.x = *(unsigned*)&h0; u.y = *(unsigned*)&h1;
                u.z = *(unsigned*)&h2; u.w = *(unsigned*)&h3;
                *(uint4*)&hsm[b * WK + seg * 8] = u;
            }
        } else {
            for (int i = tid; i < 1024; i += GRU_THREADS) {
                int b = i >> 7, seg = i & 127;
                *(uint4*)&hsm[b * WK + seg * 8] = h16v[b * 128 + seg];
            }
        }
        __syncthreads();

        {
            float cz0 = 0, cz1 = 0, cz2 = 0, cz3 = 0;
            float cr0 = 0, cr1 = 0, cr2 = 0, cr3 = 0;
#pragma unroll
            for (int c = 0; c < 4; c++) {
                int k0 = kbase + c * 16;
                unsigned a0 = *(const unsigned*)&hsm[frow * WK + k0 + fk];
                unsigned a2 = *(const unsigned*)&hsm[frow * WK + k0 + 8 + fk];
                unsigned bz0 = *(const unsigned*)&wsm[frow * WK + k0 + fk];
                unsigned bz1 = *(const unsigned*)&wsm[frow * WK + k0 + 8 + fk];
                unsigned br0 = *(const unsigned*)&wsm[(8 + frow) * WK + k0 + fk];
                unsigned br1 = *(const unsigned*)&wsm[(8 + frow) * WK + k0 + 8 + fk];
                mma16816(cz0, cz1, cz2, cz3, a0, 0u, a2, 0u, bz0, bz1);
                mma16816(cr0, cr1, cr2, cr3, a0, 0u, a2, 0u, br0, br1);
            }
            pbuf[(warp * 2 + 0) * 64 + frow * 8 + fk]     = cz0;
            pbuf[(warp * 2 + 0) * 64 + frow * 8 + fk + 1] = cz1;
            pbuf[(warp * 2 + 1) * 64 + frow * 8 + fk]     = cr0;
            pbuf[(warp * 2 + 1) * 64 + frow * 8 + fk + 1] = cr1;
        }
        if (tid < 192) xbuf[tid] = xpre;
        __syncthreads();

        if (tid < 128) {
            int b = tid >> 4, jj = tid & 15;
            int g = jj >> 3, j = jj & 7;
            float s = 0.f;
#pragma unroll
            for (int w = 0; w < 16; w++) s += pbuf[(w * 2 + g) * 64 + b * 8 + j];
            if (g == 0) {
                float z = 1.f / (1.f + __expf(-(s + xbuf[b * 24 + j] + bsm[j])));
                zsm[b * 8 + j] = z;
            } else {
                float r = 1.f / (1.f + __expf(-(s + xbuf[b * 24 + 8 + j] + bsm[8 + j])));
                g_rh16[b * NHID + colbase + j] = __float2half(r * hpsm[b * 8 + j]);
            }
        }
        group_barrier(&g_ctrs[0]);

        for (int i = tid; i < 1024; i += GRU_THREADS) {
            int b = i >> 7, seg = i & 127;
            *(uint4*)&hsm[b * WK + seg * 8] = rh16v[b * 128 + seg];
        }
        __syncthreads();

        {
            float c0 = 0, c1 = 0, c2 = 0, c3 = 0;
#pragma unroll
            for (int c = 0; c < 4; c++) {
                int k0 = kbase + c * 16;
                unsigned a0 = *(const unsigned*)&hsm[frow * WK + k0 + fk];
                unsigned a2 = *(const unsigned*)&hsm[frow * WK + k0 + 8 + fk];
                unsigned bh0 = *(const unsigned*)&wsm[(16 + frow) * WK + k0 + fk];
                unsigned bh1 = *(const unsigned*)&wsm[(16 + frow) * WK + k0 + 8 + fk];
                mma16816(c0, c1, c2, c3, a0, 0u, a2, 0u, bh0, bh1);
            }
            pbuf[warp * 2 * 64 + frow * 8 + fk]     = c0;
            pbuf[warp * 2 * 64 + frow * 8 + fk + 1] = c1;
        }
        __syncthreads();

        if (tid < 64) {
            int b = tid >> 3, j = tid & 7;
            float s = 0.f;
#pragma unroll
            for (int w = 0; w < 16; w++) s += pbuf[w * 2 * 64 + b * 8 + j];
            float hbar  = tanhf(s + xbuf[b * 24 + 16 + j] + bsm[16 + j]);
            float hprev = hpsm[tid];
            float z     = zsm[tid];
            float hn    = hprev + z * (hbar - hprev);
            hpsm[tid] = hn;
            __half hh = __float2half(hn);
            int c = colbase + j;
            g_h16[b * NHID + c] = hh;
            g_hs[(size_t)(b * TSTEPS + t) * NHID + c] = hh;
        }
        group_barrier(&g_ctrs[128]);
    }
}

// ---------------------------------------------------------------------------
// Prep kernels
// ---------------------------------------------------------------------------
__global__ void cvt_half2(const float2* __restrict__ src, __half2* __restrict__ dst, int n2) {
    int i = blockIdx.x * blockDim.x + threadIdx.x;
    int stride = gridDim.x * blockDim.x;
    for (; i < n2; i += stride) {
        float2 v = src[i];
        dst[i] = __floats2half2_rn(v.x, v.y);
    }
}

__global__ void build_wx(const float* __restrict__ Wz, const float* __restrict__ Wr,
                         const float* __restrict__ Wh, __half* __restrict__ dst) {
    int i = blockIdx.x * blockDim.x + threadIdx.x;
    if (i >= NEMBD * NG3) return;
    int k = i / NG3, c = i - k * NG3;
    int g = c >> 10, j = c & 1023;
    const float* W = (g == 0) ? Wz : ((g == 1) ? Wr : Wh);
    dst[i] = __float2half(W[(size_t)k * NHID + j]);
}

__global__ void gather_emb(const int* __restrict__ idx, const float* __restrict__ wte,
                           __half* __restrict__ dst) {
    int r = blockIdx.x;
    int tok = idx[r];
    float4 v = ((const float4*)(wte + (size_t)tok * NEMBD))[threadIdx.x];
    __half2* d = (__half2*)(dst + (size_t)r * NEMBD);
    d[threadIdx.x * 2]     = __floats2half2_rn(v.x, v.y);
    d[threadIdx.x * 2 + 1] = __floats2half2_rn(v.z, v.w);
}

// ---------------------------------------------------------------------------
// fp16 tensor-core GEMM with SOFTWARE PIPELINE (register double-buffer):
// while computing chunk k from SMEM, chunk k+1's tiles are in flight to regs.
// C[M,NCOLS] = A[M,KDIM] * B[KDIM,NCOLS] (+bias). 128x128x32 tiles, 8 warps.
// ---------------------------------------------------------------------------
#define AS_STRIDE 40
#define BS_STRIDE 42

template<int KDIM, int NCOLS2, bool HAS_BIAS>
__global__ void __launch_bounds__(256)
gemm_kernel(const __half* __restrict__ A, const __half* __restrict__ Bw,
            const float* __restrict__ bias, float* __restrict__ C) {
    const int bx = blockIdx.x, by = blockIdx.y;
    const int tid = threadIdx.x, warp = tid >> 5, lane = tid & 31;
    const int wm = warp >> 2, wn = warp & 3;
    __shared__ __half As[128 * AS_STRIDE];
    __shared__ __half Bs[128 * BS_STRIDE];

    float acc[4][4][4];
#pragma unroll
    for (int a = 0; a < 4; a++)
#pragma unroll
        for (int b = 0; b < 4; b++)
#pragma unroll
            for (int c = 0; c < 4; c++) acc[a][b][c] = 0.f;

    const int m0 = by * 128, n0 = bx * 128;

    // per-thread staging coordinates
    const int ar0 = tid >> 1, as0 = (tid & 1) * 2;          // A: rows, 2 uint4 each
    const int bk0 = tid >> 3, bn0 = (tid & 7) * 8;          // B: 8 half2 each (2 k-rows x ... )
    // A prefetch regs: 2 x uint4 ; B prefetch regs: 8 x half2
    uint4  av[2];
    __half2 bv[8];

    // ---- prologue: load chunk 0 ----
    {
        const int k0 = 0;
#pragma unroll
        for (int u = 0; u < 2; u++)
            av[u] = *(const uint4*)&A[(size_t)(m0 + ar0) * KDIM + k0 + (as0 + u) * 8];
#pragma unroll
        for (int u = 0; u < 8; u++) {
            int i = tid + u * 256;                 // 0..2047
            int k = i >> 6, np = i & 63;
            bv[u] = *(const __half2*)(Bw + (size_t)(k0 + k) * NCOLS2 + n0 + np * 2);
        }
        // store to SMEM
#pragma unroll
        for (int u = 0; u < 2; u++)
            *(uint4*)&As[ar0 * AS_STRIDE + (as0 + u) * 8] = av[u];
#pragma unroll
        for (int u = 0; u < 8; u++) {
            int i = tid + u * 256;
            int k = i >> 6, np = i & 63;
            Bs[(np * 2)     * BS_STRIDE + k] = __low2half(bv[u]);
            Bs[(np * 2 + 1) * BS_STRIDE + k] = __high2half(bv[u]);
        }
    }
    __syncthreads();

    const int NCHUNK = KDIM / 32;
    for (int chunk = 0; chunk < NCHUNK; chunk++) {
        // ---- prefetch next chunk into registers (overlaps with compute) ----
        if (chunk + 1 < NCHUNK) {
            const int k0 = (chunk + 1) * 32;
#pragma unroll
            for (int u = 0; u < 2; u++)
                av[u] = *(const uint4*)&A[(size_t)(m0 + ar0) * KDIM + k0 + (as0 + u) * 8];
#pragma unroll
            for (int u = 0; u < 8; u++) {
                int i = tid + u * 256;
                int k = i >> 6, np = i & 63;
                bv[u] = *(const __half2*)(Bw + (size_t)(k0 + k) * NCOLS2 + n0 + np * 2);
            }
        }

        // ---- compute current chunk from SMEM ----
#pragma unroll
        for (int kk = 0; kk < 2; kk++) {
            unsigned a[4][4], b[4][2];
            const int kc = kk * 16 + (lane & 3) * 2;
            const int r  = lane >> 2;
#pragma unroll
            for (int mt = 0; mt < 4; mt++) {
                int rr = wm * 64 + mt * 16 + r;
                a[mt][0] = *(const unsigned*)&As[rr * AS_STRIDE + kc];
                a[mt][1] = *(const unsigned*)&As[(rr + 8) * AS_STRIDE + kc];
                a[mt][2] = *(const unsigned*)&As[rr * AS_STRIDE + kc + 8];
                a[mt][3] = *(const unsigned*)&As[(rr + 8) * AS_STRIDE + kc + 8];
            }
#pragma unroll
            for (int nt = 0; nt < 4; nt++) {
                int nn = wn * 32 + nt * 8 + r;
                b[nt][0] = *(const unsigned*)&Bs[nn * BS_STRIDE + kc];
                b[nt][1] = *(const unsigned*)&Bs[nn * BS_STRIDE + kc + 8];
            }
#pragma unroll
            for (int mt = 0; mt < 4; mt++)
#pragma unroll
                for (int nt = 0; nt < 4; nt++)
                    mma16816(acc[mt][nt][0], acc[mt][nt][1], acc[mt][nt][2], acc[mt][nt][3],
                             a[mt][0], a[mt][1], a[mt][2], a[mt][3], b[nt][0], b[nt][1]);
        }
        __syncthreads();

        // ---- store prefetched regs to SMEM for next iteration ----
        if (chunk + 1 < NCHUNK) {
#pragma unroll
            for (int u = 0; u < 2; u++)
                *(uint4*)&As[ar0 * AS_STRIDE + (as0 + u) * 8] = av[u];
#pragma unroll
            for (int u = 0; u < 8; u++) {
                int i = tid + u * 256;
                int k = i >> 6, np = i & 63;
                Bs[(np * 2)     * BS_STRIDE + k] = __low2half(bv[u]);
                Bs[(np * 2 + 1) * BS_STRIDE + k] = __high2half(bv[u]);
            }
            __syncthreads();
        }
    }

    // ---- epilogue ----
#pragma unroll
    for (int mt = 0; mt < 4; mt++) {
#pragma unroll
        for (int nt = 0; nt < 4; nt++) {
            int gr = m0 + wm * 64 + mt * 16 + (lane >> 2);
            int gc = n0 + wn * 32 + nt * 8 + (lane & 3) * 2;
            float b0 = 0.f, b1 = 0.f;
            if (HAS_BIAS) { b0 = bias[gc]; b1 = bias[gc + 1]; }
            float2 v0 = make_float2(acc[mt][nt][0] + b0, acc[mt][nt][1] + b1);
            float2 v1 = make_float2(acc[mt][nt][2] + b0, acc[mt][nt][3] + b1);
            *(float2*)&C[(size_t)gr * NCOLS2 + gc]       = v0;
            *(float2*)&C[(size_t)(gr + 8) * NCOLS2 + gc] = v1;
        }
    }
}

// ---------------------------------------------------------------------------
// Loss
// ---------------------------------------------------------------------------
__global__ void __launch_bounds__(256)
loss_kernel(const float* __restrict__ logits, const int* __restrict__ targets,
            float* __restrict__ out_loss) {
    const int row = blockIdx.x;
    const float* lr = logits + (size_t)row * VOCAB;
    const int tid = threadIdx.x;

    float m = -1e30f, s = 0.f;
    for (int i = tid; i < VOCAB; i += 256) {
        float v = lr[i];
        float nm = fmaxf(m, v);
        s = s * __expf(m - nm) + __expf(v - nm);
        m = nm;
    }
    __shared__ float sm_m[256], sm_s[256];
    sm_m[tid] = m; sm_s[tid] = s;
    __syncthreads();
    for (int off = 128; off > 0; off >>= 1) {
        if (tid < off) {
            float m2 = sm_m[tid + off], s2 = sm_s[tid + off];
            float m1 = sm_m[tid],       s1 = sm_s[tid];
            float nm = fmaxf(m1, m2);
            sm_s[tid] = s1 * __expf(m1 - nm) + s2 * __expf(m2 - nm);
            sm_m[tid] = nm;
        }
        __syncthreads();
    }
    if (tid == 0) {
        float lse = sm_m[0] + logf(sm_s[0]);
        float tl  = lr[targets[row]];
        atomicAdd(out_loss, (lse - tl) * (1.0f / (float)NROWS));
    }
}

// ---------------------------------------------------------------------------
// Host entry
// ---------------------------------------------------------------------------
extern "C" void kernel_launch(void* const* d_in, const int* in_sizes, int n_in,
                              void* d_out, int out_size) {
    const int*   idx   = (const int*)d_in[0];
    const int*   tgt   = (const int*)d_in[1];
    const float* wte   = (const float*)d_in[2];
    const float* start = (const float*)d_in[3];
    const float* Wz    = (const float*)d_in[4];
    const float* bz    = (const float*)d_in[5];
    const float* Wr    = (const float*)d_in[6];
    const float* br    = (const float*)d_in[7];
    const float* Wh    = (const float*)d_in[8];
    const float* bh    = (const float*)d_in[9];
    const float* lmW   = (const float*)d_in[10];
    const float* lmb   = (const float*)d_in[11];

    void *p_hs, *p_wlm, *p_fb, *p_emb, *p_wx, *p_xp;
    cudaGetSymbolAddress(&p_hs,  g_hs);
    cudaGetSymbolAddress(&p_wlm, g_wlm);
    cudaGetSymbolAddress(&p_fb,  g_logits_fb);
    cudaGetSymbolAddress(&p_emb, g_emb);
    cudaGetSymbolAddress(&p_wx,  g_wx);
    cudaGetSymbolAddress(&p_xp,  g_xp);
    __half* d_hs  = (__half*)p_hs;
    __half* d_wlm = (__half*)p_wlm;
    float*  d_fb  = (float*)p_fb;
    __half* d_emb = (__half*)p_emb;
    __half* d_wx  = (__half*)p_wx;
    float*  d_xp  = (float*)p_xp;

    cudaFuncSetAttribute(gru_kernel, cudaFuncAttributeMaxDynamicSharedMemorySize,
                         GRU_SMEM_BYTES);

    build_wx<<<(NEMBD * NG3 + 255) / 256, 256>>>(Wz, Wr, Wh, d_wx);
    gather_emb<<<NROWS, 128>>>(idx, wte, d_emb);

    gemm_kernel<NEMBD, NG3, false><<<dim3(NG3 / 128, NROWS / 128), 256>>>(
        d_emb, d_wx, nullptr, d_xp);

    gru_kernel<<<GRU_BLOCKS, GRU_THREADS, GRU_SMEM_BYTES>>>(start, Wz, bz, Wr, br, Wh, bh);

    cvt_half2<<<4096, 256>>>((const float2*)lmW, (__half2*)d_wlm, (NHID * VOCAB) / 2);
    const long long NL = (long long)NROWS * VOCAB;
    float* fo = (float*)d_out;
    float* logits = ((long long)out_size >= NL) ? fo : d_fb;
    gemm_kernel<NHID, VOCAB, true><<<dim3(VOCAB / 128, NROWS / 128), 256>>>(
        d_hs, d_wlm, lmb, logits);

    float* loss_ptr = nullptr;
    if ((long long)out_size >= NL + 1)      loss_ptr = fo + NL;
    else if ((long long)out_size < NL)      loss_ptr = fo;
    if (loss_ptr) {
        cudaMemsetAsync(loss_ptr, 0, sizeof(float));
        loss_kernel<<<NROWS, 256>>>(logits, tgt, loss_ptr);
    }
}

// round 11
// speedup vs baseline: 1.6456x; 1.0496x over previous
#include <cuda_runtime.h>
#include <cuda_fp16.h>
#include <cstdint>

// ---------------------------------------------------------------------------
// Problem constants
// ---------------------------------------------------------------------------
#define BATCH   8
#define TSTEPS  512
#define NEMBD   512
#define NHID    1024
#define VOCAB   32000
#define NROWS   (BATCH * TSTEPS)        // 4096
#define NG3     (3 * NHID)              // 3072

// GRU persistent kernel config (R4 exact)
#define GRU_BLOCKS   128
#define GRU_THREADS  512
#define WK          1032

#define WSM_BYTES   (24 * WK * 2)
#define HSM_BYTES   (8  * WK * 2)
#define PBUF_FLOATS (16 * 2 * 64)
#define XBUF_FLOATS 192
#define ZSM_FLOATS  64
#define HPSM_FLOATS 64
#define BSM_FLOATS  24
#define GRU_SMEM_BYTES (WSM_BYTES + HSM_BYTES + \
    (PBUF_FLOATS + XBUF_FLOATS + ZSM_FLOATS + HPSM_FLOATS + BSM_FLOATS) * 4)

// ---------------------------------------------------------------------------
// Device scratch (host resolves ONLY via cudaGetSymbolAddress)
// ---------------------------------------------------------------------------
__device__ __half              g_h16[BATCH * NHID];
__device__ __half              g_rh16[BATCH * NHID];
__device__ __half              g_hs[(size_t)NROWS * NHID];    // hidden states fp16
__device__ __half              g_wlm[(size_t)NHID * VOCAB];   // lm weights TRANSPOSED [32000][1024]
__device__ __half              g_emb[(size_t)NROWS * NEMBD];  // embeddings fp16
__device__ __half              g_wx[(size_t)NEMBD * NG3];     // x-weights TRANSPOSED [3072][512]
__device__ float               g_xp[(size_t)NROWS * NG3];     // x-projections fp32
__device__ unsigned long long  g_ctrs[256];
__device__ float               g_logits_fb[(size_t)NROWS * VOCAB];

// ---------------------------------------------------------------------------
// Grid barrier (R4 exact)
// ---------------------------------------------------------------------------
__device__ __forceinline__ void group_barrier(unsigned long long* ctr) {
    __syncthreads();
    if (threadIdx.x == 0) {
        unsigned long long one = 1ULL, old;
        asm volatile("atom.add.release.gpu.global.u64 %0, [%1], %2;"
                     : "=l"(old) : "l"(ctr), "l"(one) : "memory");
        unsigned long long target = ((old + 1ULL + (GRU_BLOCKS - 1)) / GRU_BLOCKS) * GRU_BLOCKS;
        unsigned long long cur;
        asm volatile("ld.acquire.gpu.global.u64 %0, [%1];" : "=l"(cur) : "l"(ctr) : "memory");
        while (cur < target) {
            __nanosleep(64);
            asm volatile("ld.acquire.gpu.global.u64 %0, [%1];" : "=l"(cur) : "l"(ctr) : "memory");
        }
    }
    __syncthreads();
}

// ---------------------------------------------------------------------------
// mma m16n8k16 f16 -> f32
// ---------------------------------------------------------------------------
__device__ __forceinline__ void mma16816(float& c0, float& c1, float& c2, float& c3,
                                         unsigned a0, unsigned a1, unsigned a2, unsigned a3,
                                         unsigned b0, unsigned b1) {
    asm volatile(
        "mma.sync.aligned.m16n8k16.row.col.f32.f16.f16.f32 "
        "{%0,%1,%2,%3}, {%4,%5,%6,%7}, {%8,%9}, {%0,%1,%2,%3};\n"
        : "+f"(c0), "+f"(c1), "+f"(c2), "+f"(c3)
        : "r"(a0), "r"(a1), "r"(a2), "r"(a3), "r"(b0), "r"(b1));
}

// ---------------------------------------------------------------------------
// Persistent GRU scan — R4 EXACT (measured 2.431 ms, reproducible)
// ---------------------------------------------------------------------------
__global__ void __launch_bounds__(GRU_THREADS, 1)
gru_kernel(const float* __restrict__ start,
           const float* __restrict__ Wz, const float* __restrict__ bz,
           const float* __restrict__ Wr, const float* __restrict__ br,
           const float* __restrict__ Wh, const float* __restrict__ bh) {
    extern __shared__ char smem[];
    __half* wsm  = (__half*)smem;
    __half* hsm  = (__half*)(smem + WSM_BYTES);
    float*  pbuf = (float*)(smem + WSM_BYTES + HSM_BYTES);
    float*  xbuf = pbuf + PBUF_FLOATS;
    float*  zsm  = xbuf + XBUF_FLOATS;
    float*  hpsm = zsm + ZSM_FLOATS;
    float*  bsm  = hpsm + HPSM_FLOATS;

    const int tid     = threadIdx.x;
    const int warp    = tid >> 5;
    const int lane    = tid & 31;
    const int colbase = blockIdx.x * 8;

    for (int i = tid; i < 24 * 1024; i += GRU_THREADS) {
        int j = i >> 10, k = i & 1023;
        int g = j >> 3;
        const float* W = (g == 0) ? Wz : ((g == 1) ? Wr : Wh);
        wsm[j * WK + k] = __float2half(W[(size_t)(NEMBD + k) * NHID + colbase + (j & 7)]);
    }
    if (tid < 24) bsm[tid] = (tid < 8 ? bz[colbase + tid]
                              : tid < 16 ? br[colbase + tid - 8]
                                         : bh[colbase + tid - 16]);
    if (tid < 64) hpsm[tid] = start[colbase + (tid & 7)];

    const float4* start4 = (const float4*)start;
    const uint4*  h16v   = (const uint4*)g_h16;
    const uint4*  rh16v  = (const uint4*)g_rh16;

    const int xb   = tid / 24;
    const int xrem = tid - xb * 24;

    const int frow = lane >> 2;
    const int fk   = (lane & 3) * 2;
    const int kbase = warp * 64;

    for (int t = 0; t < TSTEPS; ++t) {
        float xpre = 0.f;
        if (tid < 192)
            xpre = g_xp[((size_t)(xb * TSTEPS + t)) * NG3 + (xrem >> 3) * NHID + colbase + (xrem & 7)];

        if (t == 0) {
            for (int i = tid; i < 1024; i += GRU_THREADS) {
                int b = i >> 7, seg = i & 127;
                float4 v0 = start4[seg * 2], v1 = start4[seg * 2 + 1];
                __half2 h0 = __floats2half2_rn(v0.x, v0.y);
                __half2 h1 = __floats2half2_rn(v0.z, v0.w);
                __half2 h2 = __floats2half2_rn(v1.x, v1.y);
                __half2 h3 = __floats2half2_rn(v1.z, v1.w);
                uint4 u;
                u.x = *(unsigned*)&h0; u.y = *(unsigned*)&h1;
                u.z = *(unsigned*)&h2; u.w = *(unsigned*)&h3;
                *(uint4*)&hsm[b * WK + seg * 8] = u;
            }
        } else {
            for (int i = tid; i < 1024; i += GRU_THREADS) {
                int b = i >> 7, seg = i & 127;
                *(uint4*)&hsm[b * WK + seg * 8] = h16v[b * 128 + seg];
            }
        }
        __syncthreads();

        {
            float cz0 = 0, cz1 = 0, cz2 = 0, cz3 = 0;
            float cr0 = 0, cr1 = 0, cr2 = 0, cr3 = 0;
#pragma unroll
            for (int c = 0; c < 4; c++) {
                int k0 = kbase + c * 16;
                unsigned a0 = *(const unsigned*)&hsm[frow * WK + k0 + fk];
                unsigned a2 = *(const unsigned*)&hsm[frow * WK + k0 + 8 + fk];
                unsigned bz0 = *(const unsigned*)&wsm[frow * WK + k0 + fk];
                unsigned bz1 = *(const unsigned*)&wsm[frow * WK + k0 + 8 + fk];
                unsigned br0 = *(const unsigned*)&wsm[(8 + frow) * WK + k0 + fk];
                unsigned br1 = *(const unsigned*)&wsm[(8 + frow) * WK + k0 + 8 + fk];
                mma16816(cz0, cz1, cz2, cz3, a0, 0u, a2, 0u, bz0, bz1);
                mma16816(cr0, cr1, cr2, cr3, a0, 0u, a2, 0u, br0, br1);
            }
            pbuf[(warp * 2 + 0) * 64 + frow * 8 + fk]     = cz0;
            pbuf[(warp * 2 + 0) * 64 + frow * 8 + fk + 1] = cz1;
            pbuf[(warp * 2 + 1) * 64 + frow * 8 + fk]     = cr0;
            pbuf[(warp * 2 + 1) * 64 + frow * 8 + fk + 1] = cr1;
        }
        if (tid < 192) xbuf[tid] = xpre;
        __syncthreads();

        if (tid < 128) {
            int b = tid >> 4, jj = tid & 15;
            int g = jj >> 3, j = jj & 7;
            float s = 0.f;
#pragma unroll
            for (int w = 0; w < 16; w++) s += pbuf[(w * 2 + g) * 64 + b * 8 + j];
            if (g == 0) {
                float z = 1.f / (1.f + __expf(-(s + xbuf[b * 24 + j] + bsm[j])));
                zsm[b * 8 + j] = z;
            } else {
                float r = 1.f / (1.f + __expf(-(s + xbuf[b * 24 + 8 + j] + bsm[8 + j])));
                g_rh16[b * NHID + colbase + j] = __float2half(r * hpsm[b * 8 + j]);
            }
        }
        group_barrier(&g_ctrs[0]);

        for (int i = tid; i < 1024; i += GRU_THREADS) {
            int b = i >> 7, seg = i & 127;
            *(uint4*)&hsm[b * WK + seg * 8] = rh16v[b * 128 + seg];
        }
        __syncthreads();

        {
            float c0 = 0, c1 = 0, c2 = 0, c3 = 0;
#pragma unroll
            for (int c = 0; c < 4; c++) {
                int k0 = kbase + c * 16;
                unsigned a0 = *(const unsigned*)&hsm[frow * WK + k0 + fk];
                unsigned a2 = *(const unsigned*)&hsm[frow * WK + k0 + 8 + fk];
                unsigned bh0 = *(const unsigned*)&wsm[(16 + frow) * WK + k0 + fk];
                unsigned bh1 = *(const unsigned*)&wsm[(16 + frow) * WK + k0 + 8 + fk];
                mma16816(c0, c1, c2, c3, a0, 0u, a2, 0u, bh0, bh1);
            }
            pbuf[warp * 2 * 64 + frow * 8 + fk]     = c0;
            pbuf[warp * 2 * 64 + frow * 8 + fk + 1] = c1;
        }
        __syncthreads();

        if (tid < 64) {
            int b = tid >> 3, j = tid & 7;
            float s = 0.f;
#pragma unroll
            for (int w = 0; w < 16; w++) s += pbuf[w * 2 * 64 + b * 8 + j];
            float hbar  = tanhf(s + xbuf[b * 24 + 16 + j] + bsm[16 + j]);
            float hprev = hpsm[tid];
            float z     = zsm[tid];
            float hn    = hprev + z * (hbar - hprev);
            hpsm[tid] = hn;
            __half hh = __float2half(hn);
            int c = colbase + j;
            g_h16[b * NHID + c] = hh;
            g_hs[(size_t)(b * TSTEPS + t) * NHID + c] = hh;
        }
        group_barrier(&g_ctrs[128]);
    }
}

// ---------------------------------------------------------------------------
// Prep: tiled transpose + fp32->fp16 : src [SK][SN] f32 -> dst [SN][SK] f16
// ---------------------------------------------------------------------------
__global__ void __launch_bounds__(256)
transpose_fp16(const float* __restrict__ src, __half* __restrict__ dst,
               int SK, int SN) {
    __shared__ float tile[32][33];
    int n0 = blockIdx.x * 32, k0 = blockIdx.y * 32;
    int tx = threadIdx.x & 31, ty = threadIdx.x >> 5;
    for (int r = ty; r < 32; r += 8)
        tile[r][tx] = src[(size_t)(k0 + r) * SN + n0 + tx];
    __syncthreads();
    for (int r = ty; r < 32; r += 8)
        dst[(size_t)(n0 + r) * SK + k0 + tx] = __float2half(tile[tx][r]);
}

__global__ void gather_emb(const int* __restrict__ idx, const float* __restrict__ wte,
                           __half* __restrict__ dst) {
    int r = blockIdx.x;
    int tok = idx[r];
    float4 v = ((const float4*)(wte + (size_t)tok * NEMBD))[threadIdx.x];
    __half2* d = (__half2*)(dst + (size_t)r * NEMBD);
    d[threadIdx.x * 2]     = __floats2half2_rn(v.x, v.y);
    d[threadIdx.x * 2 + 1] = __floats2half2_rn(v.z, v.w);
}

// ---------------------------------------------------------------------------
// HMMA GEMM v2: C[M,NCOLS] = A[M,KDIM] @ Bt[NCOLS,KDIM]^T (+bias)
// 128x256 block tile, 8 warps (2x4) with 64x64 warp tiles, K-chunk 32,
// cp.async 2-stage double buffering. All dims divide evenly.
// ---------------------------------------------------------------------------
#define G2_STRIDE 40                              // halves per staged row (32+8 pad)
#define G2_A_HALVES (128 * G2_STRIDE)             // 5120
#define G2_B_HALVES (256 * G2_STRIDE)             // 10240
#define G2_STAGE_HALVES (G2_A_HALVES + G2_B_HALVES) // 15360
#define G2_SMEM_BYTES (2 * G2_STAGE_HALVES * 2)   // 61440

__device__ __forceinline__ void cp_async16(uint32_t smaddr, const void* gptr) {
    asm volatile("cp.async.cg.shared.global [%0], [%1], 16;\n"
                 :: "r"(smaddr), "l"(gptr));
}
__device__ __forceinline__ void cp_commit() {
    asm volatile("cp.async.commit_group;\n" ::: "memory");
}
template<int N>
__device__ __forceinline__ void cp_wait() {
    asm volatile("cp.async.wait_group %0;\n" :: "n"(N) : "memory");
}

template<int KDIM, bool HAS_BIAS>
__global__ void __launch_bounds__(256, 1)
gemm2(const __half* __restrict__ A, const __half* __restrict__ Bt,
      const float* __restrict__ bias, float* __restrict__ C, int NCOLS) {
    extern __shared__ __half sm[];
    const int tid = threadIdx.x, warp = tid >> 5, lane = tid & 31;
    const int wm = warp >> 2, wn = warp & 3;              // 2 x 4 warps, 64x64 tiles
    const int m0 = blockIdx.y * 128, n0 = blockIdx.x * 256;

    float acc[4][8][4];
#pragma unroll
    for (int a = 0; a < 4; a++)
#pragma unroll
        for (int b = 0; b < 8; b++)
#pragma unroll
            for (int c = 0; c < 4; c++) acc[a][b][c] = 0.f;

    // staging coordinates (16B granules)
    const int aIdx0 = tid * 2;            // 512 A granules: row=idx>>2, seg=idx&3
    const int bIdx0 = tid * 4;            // 1024 B granules

    auto stage_u32 = [&](int s, int halfOff) -> uint32_t {
        return (uint32_t)__cvta_generic_to_shared(sm + s * G2_STAGE_HALVES + halfOff);
    };

    // issue one chunk's cp.asyncs into stage s
    auto issue = [&](int ch, int s) {
        const int k0 = ch * 32;
#pragma unroll
        for (int u = 0; u < 2; u++) {
            int idx = aIdx0 + u;
            int row = idx >> 2, seg = idx & 3;
            cp_async16(stage_u32(s, row * G2_STRIDE + seg * 8),
                       &A[(size_t)(m0 + row) * KDIM + k0 + seg * 8]);
        }
#pragma unroll
        for (int u = 0; u < 4; u++) {
            int idx = bIdx0 + u;
            int row = idx >> 2, seg = idx & 3;
            cp_async16(stage_u32(s, G2_A_HALVES + row * G2_STRIDE + seg * 8),
                       &Bt[(size_t)(n0 + row) * KDIM + k0 + seg * 8]);
        }
        cp_commit();
    };

    issue(0, 0);

    const int NCHUNK = KDIM / 32;
    for (int ch = 0; ch < NCHUNK; ch++) {
        const int s = ch & 1;
        if (ch + 1 < NCHUNK) { issue(ch + 1, s ^ 1); cp_wait<1>(); }
        else                 { cp_wait<0>(); }
        __syncthreads();

        const __half* As = sm + s * G2_STAGE_HALVES;
        const __half* Bs = As + G2_A_HALVES;

#pragma unroll
        for (int kk = 0; kk < 2; kk++) {
            const int kc = kk * 16 + (lane & 3) * 2;
            const int r  = lane >> 2;
            unsigned a[4][4], b[8][2];
#pragma unroll
            for (int mt = 0; mt < 4; mt++) {
                int rr = wm * 64 + mt * 16 + r;
                a[mt][0] = *(const unsigned*)&As[rr * G2_STRIDE + kc];
                a[mt][1] = *(const unsigned*)&As[(rr + 8) * G2_STRIDE + kc];
                a[mt][2] = *(const unsigned*)&As[rr * G2_STRIDE + kc + 8];
                a[mt][3] = *(const unsigned*)&As[(rr + 8) * G2_STRIDE + kc + 8];
            }
#pragma unroll
            for (int nt = 0; nt < 8; nt++) {
                int nn = wn * 64 + nt * 8 + r;
                b[nt][0] = *(const unsigned*)&Bs[nn * G2_STRIDE + kc];
                b[nt][1] = *(const unsigned*)&Bs[nn * G2_STRIDE + kc + 8];
            }
#pragma unroll
            for (int mt = 0; mt < 4; mt++)
#pragma unroll
                for (int nt = 0; nt < 8; nt++)
                    mma16816(acc[mt][nt][0], acc[mt][nt][1], acc[mt][nt][2], acc[mt][nt][3],
                             a[mt][0], a[mt][1], a[mt][2], a[mt][3], b[nt][0], b[nt][1]);
        }
        __syncthreads();   // all warps done reading stage s before it is reloaded
    }

    // epilogue
#pragma unroll
    for (int mt = 0; mt < 4; mt++) {
#pragma unroll
        for (int nt = 0; nt < 8; nt++) {
            int gr = m0 + wm * 64 + mt * 16 + (lane >> 2);
            int gc = n0 + wn * 64 + nt * 8 + (lane & 3) * 2;
            float b0 = 0.f, b1 = 0.f;
            if (HAS_BIAS) { b0 = bias[gc]; b1 = bias[gc + 1]; }
            float2 v0 = make_float2(acc[mt][nt][0] + b0, acc[mt][nt][1] + b1);
            float2 v1 = make_float2(acc[mt][nt][2] + b0, acc[mt][nt][3] + b1);
            *(float2*)&C[(size_t)gr * NCOLS + gc]       = v0;
            *(float2*)&C[(size_t)(gr + 8) * NCOLS + gc] = v1;
        }
    }
}

// ---------------------------------------------------------------------------
// Loss
// ---------------------------------------------------------------------------
__global__ void __launch_bounds__(256)
loss_kernel(const float* __restrict__ logits, const int* __restrict__ targets,
            float* __restrict__ out_loss) {
    const int row = blockIdx.x;
    const float* lr = logits + (size_t)row * VOCAB;
    const int tid = threadIdx.x;

    float m = -1e30f, s = 0.f;
    for (int i = tid; i < VOCAB; i += 256) {
        float v = lr[i];
        float nm = fmaxf(m, v);
        s = s * __expf(m - nm) + __expf(v - nm);
        m = nm;
    }
    __shared__ float sm_m[256], sm_s[256];
    sm_m[tid] = m; sm_s[tid] = s;
    __syncthreads();
    for (int off = 128; off > 0; off >>= 1) {
        if (tid < off) {
            float m2 = sm_m[tid + off], s2 = sm_s[tid + off];
            float m1 = sm_m[tid],       s1 = sm_s[tid];
            float nm = fmaxf(m1, m2);
            sm_s[tid] = s1 * __expf(m1 - nm) + s2 * __expf(m2 - nm);
            sm_m[tid] = nm;
        }
        __syncthreads();
    }
    if (tid == 0) {
        float lse = sm_m[0] + logf(sm_s[0]);
        float tl  = lr[targets[row]];
        atomicAdd(out_loss, (lse - tl) * (1.0f / (float)NROWS));
    }
}

// ---------------------------------------------------------------------------
// Host entry
// ---------------------------------------------------------------------------
extern "C" void kernel_launch(void* const* d_in, const int* in_sizes, int n_in,
                              void* d_out, int out_size) {
    const int*   idx   = (const int*)d_in[0];
    const int*   tgt   = (const int*)d_in[1];
    const float* wte   = (const float*)d_in[2];
    const float* start = (const float*)d_in[3];
    const float* Wz    = (const float*)d_in[4];
    const float* bz    = (const float*)d_in[5];
    const float* Wr    = (const float*)d_in[6];
    const float* br    = (const float*)d_in[7];
    const float* Wh    = (const float*)d_in[8];
    const float* bh    = (const float*)d_in[9];
    const float* lmW   = (const float*)d_in[10];
    const float* lmb   = (const float*)d_in[11];

    void *p_hs, *p_wlm, *p_fb, *p_emb, *p_wx, *p_xp;
    cudaGetSymbolAddress(&p_hs,  g_hs);
    cudaGetSymbolAddress(&p_wlm, g_wlm);
    cudaGetSymbolAddress(&p_fb,  g_logits_fb);
    cudaGetSymbolAddress(&p_emb, g_emb);
    cudaGetSymbolAddress(&p_wx,  g_wx);
    cudaGetSymbolAddress(&p_xp,  g_xp);
    __half* d_hs  = (__half*)p_hs;
    __half* d_wlm = (__half*)p_wlm;
    float*  d_fb  = (float*)p_fb;
    __half* d_emb = (__half*)p_emb;
    __half* d_wx  = (__half*)p_wx;
    float*  d_xp  = (float*)p_xp;

    cudaFuncSetAttribute(gru_kernel, cudaFuncAttributeMaxDynamicSharedMemorySize,
                         GRU_SMEM_BYTES);
    cudaFuncSetAttribute(gemm2<NEMBD, false>,
                         cudaFuncAttributeMaxDynamicSharedMemorySize, G2_SMEM_BYTES);
    cudaFuncSetAttribute(gemm2<NHID, true>,
                         cudaFuncAttributeMaxDynamicSharedMemorySize, G2_SMEM_BYTES);

    // 1) transpose x-part weights -> g_wx [3072][512] (gate-major rows)
    {
        dim3 grid(NHID / 32, NEMBD / 32);
        transpose_fp16<<<grid, 256>>>(Wz, d_wx + 0 * (size_t)NHID * NEMBD, NEMBD, NHID);
        transpose_fp16<<<grid, 256>>>(Wr, d_wx + 1 * (size_t)NHID * NEMBD, NEMBD, NHID);
        transpose_fp16<<<grid, 256>>>(Wh, d_wx + 2 * (size_t)NHID * NEMBD, NEMBD, NHID);
    }
    // 2) gather embeddings
    gather_emb<<<NROWS, 128>>>(idx, wte, d_emb);

    // 3) Xproj[4096,3072] = emb @ Wx^T
    gemm2<NEMBD, false><<<dim3(NG3 / 256, NROWS / 128), 256, G2_SMEM_BYTES>>>(
        d_emb, d_wx, nullptr, d_xp, NG3);

    // 4) persistent GRU scan (R4)
    gru_kernel<<<GRU_BLOCKS, GRU_THREADS, GRU_SMEM_BYTES>>>(start, Wz, bz, Wr, br, Wh, bh);

    // 5) transpose lm weights -> g_wlm [32000][1024]
    transpose_fp16<<<dim3(VOCAB / 32, NHID / 32), 256>>>(lmW, d_wlm, NHID, VOCAB);

    // 6) LM head
    const long long NL = (long long)NROWS * VOCAB;
    float* fo = (float*)d_out;
    float* logits = ((long long)out_size >= NL) ? fo : d_fb;
    gemm2<NHID, true><<<dim3(VOCAB / 256, NROWS / 128), 256, G2_SMEM_BYTES>>>(
        d_hs, d_wlm, lmb, logits, VOCAB);

    // 7) loss
    float* loss_ptr = nullptr;
    if ((long long)out_size >= NL + 1)      loss_ptr = fo + NL;
    else if ((long long)out_size < NL)      loss_ptr = fo;
    if (loss_ptr) {
        cudaMemsetAsync(loss_ptr, 0, sizeof(float));
        loss_kernel<<<NROWS, 256>>>(logits, tgt, loss_ptr);
    }
}